// round 13
// baseline (speedup 1.0000x reference)
#include <cuda_runtime.h>
#include <cuda_bf16.h>
#include <math.h>
#include <stdint.h>

#define BATCH 8
#define CIN   256
#define HH    64
#define WW    64
#define HWX   4096
#define CO    256
#define K2    9
#define KTOT  2304
#define HO    128
#define WO    128

// ---------------- scratch ----------------
__device__ __align__(16) float    g_wcombT[KTOT*32];
__device__ __align__(16) unsigned g_wAh[CO*KTOT/2];    // deform weights hi plane [o][k/2]
__device__ __align__(16) unsigned g_wAl[CO*KTOT/2];    // lo plane
__device__ __align__(16) unsigned g_wupH[4*CO*512];    // up weights hi plane [ph][o][k/2]
__device__ __align__(16) unsigned g_wupL[4*CO*512];    // lo plane
__device__ float g_bn1s[CO], g_bn1b[CO], g_bn2s[CO], g_bn2b[CO];
__device__ __align__(16) float  g_offmask[BATCH*27*HWX];
__device__ __align__(16) float4 g_cw[BATCH*K2*HWX];
__device__ __align__(16) uint2  g_ci[BATCH*K2*HWX];
__device__ __align__(16) unsigned g_h1p[BATCH*CO*HWX]; // h1 packed bf16 hi|lo

// ---------------- helpers ----------------
__device__ __forceinline__ unsigned packbf(float v) {
    __nv_bfloat16 h = __float2bfloat16(v);
    float r = v - __bfloat162float(h);
    __nv_bfloat16 l = __float2bfloat16(r);
    return (unsigned)__bfloat16_as_ushort(h) | ((unsigned)__bfloat16_as_ushort(l) << 16);
}
__device__ __forceinline__ uint32_t smem_u32(const void* p) {
    uint32_t a;
    asm("{ .reg .u64 t; cvta.to.shared.u64 t, %1; cvt.u32.u64 %0, t; }" : "=r"(a) : "l"(p));
    return a;
}
__device__ __forceinline__ uint32_t swz(uint32_t off) { return off ^ ((off >> 3) & 0x70); }

__device__ __forceinline__ void ldm4(uint32_t* r, uint32_t addr) {
    asm volatile("ldmatrix.sync.aligned.m8n8.x4.shared.b16 {%0,%1,%2,%3}, [%4];"
        : "=r"(r[0]), "=r"(r[1]), "=r"(r[2]), "=r"(r[3]) : "r"(addr));
}
__device__ __forceinline__ void mma_bf16(float* d, const uint32_t* a, uint32_t b0, uint32_t b1) {
    asm volatile("mma.sync.aligned.m16n8k16.row.col.f32.bf16.bf16.f32 "
        "{%0,%1,%2,%3}, {%4,%5,%6,%7}, {%8,%9}, {%0,%1,%2,%3};"
        : "+f"(d[0]), "+f"(d[1]), "+f"(d[2]), "+f"(d[3])
        : "r"(a[0]), "r"(a[1]), "r"(a[2]), "r"(a[3]), "r"(b0), "r"(b1));
}
__device__ __forceinline__ void cpa16(uint32_t dst, const void* src) {
    asm volatile("cp.async.cg.shared.global [%0], [%1], 16;" :: "r"(dst), "l"(src));
}
#define CPA_COMMIT() asm volatile("cp.async.commit_group;" ::: "memory")
#define CPA_WAIT0()  asm volatile("cp.async.wait_group 0;" ::: "memory")

// ---------------- prep: BN fold ----------------
__global__ void prep_bn(const float* __restrict__ g1, const float* __restrict__ b1,
                        const float* __restrict__ m1, const float* __restrict__ v1,
                        const float* __restrict__ g2, const float* __restrict__ b2,
                        const float* __restrict__ m2, const float* __restrict__ v2) {
    int o = threadIdx.x;
    float s1 = g1[o] * rsqrtf(v1[o] + 1e-5f);
    g_bn1s[o] = s1;  g_bn1b[o] = b1[o] - m1[o]*s1;
    float s2 = g2[o] * rsqrtf(v2[o] + 1e-5f);
    g_bn2s[o] = s2;  g_bn2b[o] = b2[o] - m2[o]*s2;
}

// ---------------- prep: weight reorg + bf16 hi/lo plane split ----------------
__global__ void prep_w(const float* __restrict__ w_off, const float* __restrict__ w_mod,
                       const float* __restrict__ w_reg, const float* __restrict__ w_up) {
    int tid = blockIdx.x*blockDim.x + threadIdx.x;
    int nt  = gridDim.x*blockDim.x;
    for (int i = tid; i < KTOT*32; i += nt) {
        int kidx = i >> 5, o = i & 31;
        float v = 0.f;
        if (o < 18)      v = w_off[o*KTOT + kidx];
        else if (o < 27) v = w_mod[(o-18)*KTOT + kidx];
        g_wcombT[i] = v;
    }
    for (int i = tid; i < CO*KTOT/2; i += nt) {
        unsigned p0 = packbf(w_reg[2*i]);
        unsigned p1 = packbf(w_reg[2*i+1]);
        g_wAh[i] = __byte_perm(p0, p1, 0x5410);
        g_wAl[i] = __byte_perm(p0, p1, 0x7632);
    }
    for (int i = tid; i < 4*CO*512; i += nt) {
        int pr = i & 511;
        int o  = (i >> 9) & 255;
        int ph = i >> 17;
        int fy = ph >> 1, fx = ph & 1;
        unsigned pp[2];
        #pragma unroll
        for (int s2 = 0; s2 < 2; s2++) {
            int kidx = pr*2 + s2;
            int ci = kidx >> 2, tt = kidx & 3;
            int ty = tt >> 1, tx = tt & 1;
            int ky = fy ? (ty ? 0 : 2) : (ty ? 3 : 1);
            int kx = fx ? (tx ? 0 : 2) : (tx ? 3 : 1);
            pp[s2] = packbf(w_up[((ci*CO + o)*4 + ky)*4 + kx]);
        }
        g_wupH[i] = __byte_perm(pp[0], pp[1], 0x5410);
        g_wupL[i] = __byte_perm(pp[0], pp[1], 0x7632);
    }
}

// ---------------- kernel 1: offset + mask conv (verified) ----------------
__global__ void __launch_bounds__(256) k_offconv(const float* __restrict__ x,
                                                 const float* __restrict__ b_off,
                                                 const float* __restrict__ b_mod) {
    int h = blockIdx.x;
    int b = blockIdx.y;
    int t = threadIdx.x;
    __shared__ float4 sW4[16][8];
    __shared__ float2 sV2[16][32];
    float* sW = (float*)sW4;
    float* sV = (float*)sV2;
    int ox = t & 7, py = t >> 3;
    float acc[4][2] = {};
    const float* xb = x + (size_t)b*CIN*HWX;
    for (int t0 = 0; t0 < KTOT; t0 += 16) {
        #pragma unroll
        for (int i = 0; i < 2; i++) {
            int e = t + i*256;
            int r = e >> 5, col = e & 31;
            sW[r*32 + col] = g_wcombT[(t0+r)*32 + col];
        }
        #pragma unroll
        for (int i = 0; i < 4; i++) {
            int e = t + i*256;
            int r = e >> 6, pl = e & 63;
            int kidx = t0 + r;
            int c  = kidx / 9;
            int kk = kidx - c*9;
            int ky = kk / 3;
            int kx = kk - ky*3;
            int yy = h + ky - 1;
            int xx = pl + kx - 1;
            float v = 0.f;
            if (yy >= 0 && yy < HH && xx >= 0 && xx < WW)
                v = xb[c*HWX + yy*WW + xx];
            sV[r*64 + pl] = v;
        }
        __syncthreads();
        #pragma unroll
        for (int r = 0; r < 16; r++) {
            float4 a  = sW4[r][ox];
            float2 bv = sV2[r][py];
            acc[0][0] += a.x*bv.x; acc[0][1] += a.x*bv.y;
            acc[1][0] += a.y*bv.x; acc[1][1] += a.y*bv.y;
            acc[2][0] += a.z*bv.x; acc[2][1] += a.z*bv.y;
            acc[3][0] += a.w*bv.x; acc[3][1] += a.w*bv.y;
        }
        __syncthreads();
    }
    #pragma unroll
    for (int i = 0; i < 4; i++) {
        int o = ox*4 + i;
        if (o < 27) {
            float bias = (o < 18) ? b_off[o] : b_mod[o-18];
            #pragma unroll
            for (int j = 0; j < 2; j++) {
                int p = h*WW + py*2 + j;
                g_offmask[((size_t)b*27 + o)*HWX + p] = acc[i][j] + bias;
            }
        }
    }
}

// ---------------- kernel 1b: bilinear coefficients (verified) ----------------
__global__ void k_coef() {
    int tid = blockIdx.x*blockDim.x + threadIdx.x;
    if (tid >= BATCH*K2*HWX) return;
    int p = tid & (HWX-1);
    int k = (tid >> 12) % 9;
    int b = tid / (K2*HWX);
    const float* om = g_offmask + (size_t)b*27*HWX;
    float oyv = om[(2*k  )*HWX + p];
    float oxv = om[(2*k+1)*HWX + p];
    float z   = om[(18+k )*HWX + p];
    float m = 2.f / (1.f + expf(-z));
    int hh = p >> 6, ww = p & 63;
    float py = (float)hh - 1.f + (float)(k/3) + oyv;
    float px = (float)ww - 1.f + (float)(k%3) + oxv;
    float y0f = floorf(py), x0f = floorf(px);
    float wy1 = py - y0f,  wx1 = px - x0f;
    int y0 = (int)y0f, x0 = (int)x0f;
    int y1 = y0 + 1, x1 = x0 + 1;
    float wy0m = (y0 >= 0 && y0 < HH) ? (1.f - wy1)*m : 0.f;
    float wy1m = (y1 >= 0 && y1 < HH) ? wy1*m : 0.f;
    float wx0v = (x0 >= 0 && x0 < WW) ? (1.f - wx1) : 0.f;
    float wx1v = (x1 >= 0 && x1 < WW) ? wx1 : 0.f;
    int y0c = min(max(y0,0),HH-1), y1c = min(max(y1,0),HH-1);
    int x0c = min(max(x0,0),WW-1), x1c = min(max(x1,0),WW-1);
    float4 cw; cw.x = wy0m; cw.y = wy1m; cw.z = wx0v; cw.w = wx1v;
    g_cw[tid] = cw;
    uint2 ci;
    ci.x = (unsigned)(y0c*WW + x0c) | ((unsigned)(y0c*WW + x1c) << 16);
    ci.y = (unsigned)(y1c*WW + x0c) | ((unsigned)(y1c*WW + x1c) << 16);
    g_ci[tid] = ci;
}

// ================= GEMM tile geometry =================
// CTA 256 thr = 8 warps (2m x 4n); block M=128(o) x N=128(p); warp 64x32; KC=64.
// Buffer 64KB: AH 0 (16K), AL 16K, BH 32K, BL 48K. Double buffered.
#define BUFS   65536
#define AH_OFF 0
#define AL_OFF 16384
#define BH_OFF 32768
#define BL_OFF 49152
#define D_CW   (2*BUFS)
#define D_CI   (2*BUFS + 18432)
#define D_SMEM (2*BUFS + 18432 + 9216 + 1024)
#define U_SMEM (2*BUFS + 1024)

// ---------------- kernel 2: deform conv GEMM (HMMA, pipelined) ----------------
__global__ void __launch_bounds__(256) k_deform(const float* __restrict__ x) {
    extern __shared__ __align__(16) char smem[];
    uint32_t sraw = smem_u32(smem);
    uint32_t s0 = (sraw + 1023) & ~1023u;
    char* Bp = smem + (s0 - sraw);
    const int p0 = blockIdx.x * 128;
    const int o0 = blockIdx.y * 128;
    const int b  = blockIdx.z;
    const int t  = threadIdx.x;
    const int w  = t >> 5, lane = t & 31;
    const int m0 = (w >> 2) * 64, n0 = (w & 3) * 32;

    float4* sCW = (float4*)(Bp + D_CW);
    uint2*  sCI = (uint2*) (Bp + D_CI);
    for (int e = t; e < K2*128; e += 256) {
        int kk = e >> 7, pl = e & 127;
        int gi = (b*K2 + kk)*HWX + p0 + pl;
        sCW[e] = g_cw[gi];
        sCI[e] = g_ci[gi];
    }
    const float* xb = x + (size_t)b*CIN*HWX;
    float acc[4][4][4] = {};
    const int fpl = t & 127;
    const int fkh = t >> 7;             // 0..1: k-pair half

    auto fillA = [&](int ch, int buf) {
        int t0h = ch * 32;
        #pragma unroll
        for (int i = 0; i < 8; i++) {
            int e = t + i*256;          // 0..2047
            int plane = e >> 10;
            int rem = e & 1023;
            int orow = rem >> 3, seg = rem & 7;
            const unsigned* srcb = plane ? g_wAl : g_wAh;
            const void* src = &srcb[(o0 + orow)*(KTOT/2) + t0h + seg*4];
            uint32_t dst = s0 + buf*BUFS + (plane ? AL_OFF : AH_OFF) + swz((unsigned)(orow*128 + seg*16));
            cpa16(dst, src);
        }
    };
    auto fillB = [&](int ch, int buf) {
        int t0 = ch * 64;
        char* base = Bp + buf*BUFS;
        #pragma unroll
        for (int kp = 0; kp < 16; kp++) {
            int kpi = fkh*16 + kp;
            float v[2];
            #pragma unroll
            for (int s2 = 0; s2 < 2; s2++) {
                int kidx = t0 + kpi*2 + s2;
                int c = kidx / 9;
                int kk = kidx - c*9;
                float4 cw = sCW[kk*128 + fpl];
                uint2  ci = sCI[kk*128 + fpl];
                const float* xc = xb + c*HWX;
                v[s2] = cw.x*(cw.z*xc[ci.x & 0xFFFF] + cw.w*xc[ci.x >> 16])
                      + cw.y*(cw.z*xc[ci.y & 0xFFFF] + cw.w*xc[ci.y >> 16]);
            }
            unsigned pw0 = packbf(v[0]), pw1 = packbf(v[1]);
            unsigned off = swz((unsigned)(fpl*128 + kpi*4));
            *(unsigned*)(base + BH_OFF + off) = __byte_perm(pw0, pw1, 0x5410);
            *(unsigned*)(base + BL_OFF + off) = __byte_perm(pw0, pw1, 0x7632);
        }
    };
    auto mmaChunk = [&](int buf) {
        uint32_t sb = s0 + buf*BUFS;
        const int lrow = lane & 15;
        const int lkb  = (lane >> 4) * 16;
        #pragma unroll
        for (int ks = 0; ks < 4; ks++) {
            int kb = ks*32 + lkb;
            uint32_t bh[2][4], bl[2][4];
            #pragma unroll
            for (int nn16 = 0; nn16 < 2; nn16++) {
                uint32_t roff = (uint32_t)((n0 + nn16*16 + lrow)*128 + kb);
                ldm4(bh[nn16], sb + BH_OFF + swz(roff));
                ldm4(bl[nn16], sb + BL_OFF + swz(roff));
            }
            #pragma unroll
            for (int mm = 0; mm < 4; mm++) {
                uint32_t aoff = (uint32_t)((m0 + mm*16 + lrow)*128 + kb);
                uint32_t ah[4], al[4];
                ldm4(ah, sb + AH_OFF + swz(aoff));
                ldm4(al, sb + AL_OFF + swz(aoff));
                #pragma unroll
                for (int nn = 0; nn < 4; nn++) {
                    uint32_t b0h = bh[nn>>1][nn&1], b1h = bh[nn>>1][2+(nn&1)];
                    uint32_t b0l = bl[nn>>1][nn&1], b1l = bl[nn>>1][2+(nn&1)];
                    mma_bf16(acc[mm][nn], ah, b0h, b1h);
                    mma_bf16(acc[mm][nn], al, b0h, b1h);
                    mma_bf16(acc[mm][nn], ah, b0l, b1l);
                }
            }
        }
    };

    __syncthreads();          // coef tiles ready
    fillA(0, 0); CPA_COMMIT();
    fillB(0, 0);
    CPA_WAIT0();
    __syncthreads();
    for (int ch = 0; ch < 36; ch++) {
        int cur = ch & 1, nxt = cur ^ 1;
        if (ch < 35) { fillA(ch+1, nxt); CPA_COMMIT(); }
        mmaChunk(cur);
        if (ch < 35) { fillB(ch+1, nxt); CPA_WAIT0(); }
        __syncthreads();
    }
    // epilogue: BN1 + ReLU + pack
    #pragma unroll
    for (int mm = 0; mm < 4; mm++) {
        #pragma unroll
        for (int nn = 0; nn < 4; nn++) {
            int c0 = n0 + nn*8 + 2*(lane & 3);
            #pragma unroll
            for (int rh = 0; rh < 2; rh++) {
                int o = o0 + m0 + mm*16 + (lane >> 2) + rh*8;
                float s = g_bn1s[o], bb = g_bn1b[o];
                float v0 = acc[mm][nn][rh*2]   * s + bb;
                float v1 = acc[mm][nn][rh*2+1] * s + bb;
                v0 = v0 > 0.f ? v0 : 0.f;
                v1 = v1 > 0.f ? v1 : 0.f;
                uint2 st; st.x = packbf(v0); st.y = packbf(v1);
                *(uint2*)&g_h1p[(((size_t)b*CO + o) << 12) + p0 + c0] = st;
            }
        }
    }
}

// ---------------- kernel 3: transposed conv GEMM (HMMA, pipelined) ----------------
__global__ void __launch_bounds__(256) k_up(float* __restrict__ out) {
    extern __shared__ __align__(16) char smem[];
    uint32_t sraw = smem_u32(smem);
    uint32_t s0 = (sraw + 1023) & ~1023u;
    char* Bp = smem + (s0 - sraw);
    const int bx = blockIdx.x;
    const int o0 = blockIdx.y * 128;
    const int bz = blockIdx.z;
    const int b = bz >> 2, ph = bz & 3;
    const int fy = ph >> 1, fx = ph & 1;
    const int u0 = (bx >> 2) * 8, v0 = (bx & 3) * 16;
    const int dy1 = fy ? 1 : -1, dx1 = fx ? 1 : -1;
    const int t = threadIdx.x;
    const int w = t >> 5, lane = t & 31;
    const int m0 = (w >> 2) * 64, n0 = (w & 3) * 32;

    const unsigned* h1b = g_h1p + (((size_t)b*CO) << 12);
    const unsigned* wbH = g_wupH + ((size_t)(ph*CO) << 9);
    const unsigned* wbL = g_wupL + ((size_t)(ph*CO) << 9);

    float acc[4][4][4] = {};
    const int fpl = t & 127;
    const int fkh = t >> 7;
    const int fuu = u0 + (fpl >> 4), fvv = v0 + (fpl & 15);

    auto fillA = [&](int ch, int buf) {
        int t0h = ch * 32;
        #pragma unroll
        for (int i = 0; i < 8; i++) {
            int e = t + i*256;
            int plane = e >> 10;
            int rem = e & 1023;
            int orow = rem >> 3, seg = rem & 7;
            const unsigned* srcb = plane ? wbL : wbH;
            const void* src = &srcb[((o0 + orow) << 9) + t0h + seg*4];
            uint32_t dst = s0 + buf*BUFS + (plane ? AL_OFF : AH_OFF) + swz((unsigned)(orow*128 + seg*16));
            cpa16(dst, src);
        }
    };
    auto fillB = [&](int ch, int buf) {
        int t0 = ch * 64;
        char* base = Bp + buf*BUFS;
        #pragma unroll
        for (int kp = 0; kp < 16; kp++) {
            int kpi = fkh*16 + kp;
            int kidx0 = t0 + kpi*2;
            int ci = kidx0 >> 2;
            const unsigned* hp = h1b + ((size_t)ci << 12);
            unsigned pv[2];
            #pragma unroll
            for (int s2 = 0; s2 < 2; s2++) {
                int tt = (kidx0 + s2) & 3;
                int ty = tt >> 1, tx = tt & 1;
                int yi = fuu + (ty ? dy1 : 0);
                int xi = fvv + (tx ? dx1 : 0);
                pv[s2] = (yi >= 0 && yi < HH && xi >= 0 && xi < WW) ? hp[yi*WW + xi] : 0u;
            }
            unsigned off = swz((unsigned)(fpl*128 + kpi*4));
            *(unsigned*)(base + BH_OFF + off) = __byte_perm(pv[0], pv[1], 0x5410);
            *(unsigned*)(base + BL_OFF + off) = __byte_perm(pv[0], pv[1], 0x7632);
        }
    };
    auto mmaChunk = [&](int buf) {
        uint32_t sb = s0 + buf*BUFS;
        const int lrow = lane & 15;
        const int lkb  = (lane >> 4) * 16;
        #pragma unroll
        for (int ks = 0; ks < 4; ks++) {
            int kb = ks*32 + lkb;
            uint32_t bh[2][4], bl[2][4];
            #pragma unroll
            for (int nn16 = 0; nn16 < 2; nn16++) {
                uint32_t roff = (uint32_t)((n0 + nn16*16 + lrow)*128 + kb);
                ldm4(bh[nn16], sb + BH_OFF + swz(roff));
                ldm4(bl[nn16], sb + BL_OFF + swz(roff));
            }
            #pragma unroll
            for (int mm = 0; mm < 4; mm++) {
                uint32_t aoff = (uint32_t)((m0 + mm*16 + lrow)*128 + kb);
                uint32_t ah[4], al[4];
                ldm4(ah, sb + AH_OFF + swz(aoff));
                ldm4(al, sb + AL_OFF + swz(aoff));
                #pragma unroll
                for (int nn = 0; nn < 4; nn++) {
                    uint32_t b0h = bh[nn>>1][nn&1], b1h = bh[nn>>1][2+(nn&1)];
                    uint32_t b0l = bl[nn>>1][nn&1], b1l = bl[nn>>1][2+(nn&1)];
                    mma_bf16(acc[mm][nn], ah, b0h, b1h);
                    mma_bf16(acc[mm][nn], al, b0h, b1h);
                    mma_bf16(acc[mm][nn], ah, b0l, b1l);
                }
            }
        }
    };

    fillA(0, 0); CPA_COMMIT();
    fillB(0, 0);
    CPA_WAIT0();
    __syncthreads();
    for (int ch = 0; ch < 16; ch++) {
        int cur = ch & 1, nxt = cur ^ 1;
        if (ch < 15) { fillA(ch+1, nxt); CPA_COMMIT(); }
        mmaChunk(cur);
        if (ch < 15) { fillB(ch+1, nxt); CPA_WAIT0(); }
        __syncthreads();
    }
    // epilogue: BN2 + ReLU, strided scatter
    #pragma unroll
    for (int mm = 0; mm < 4; mm++) {
        #pragma unroll
        for (int nn = 0; nn < 4; nn++) {
            int c0 = n0 + nn*8 + 2*(lane & 3);
            int u = c0 >> 4, v = c0 & 15;
            int Y = 2*(u0 + u) + fy;
            int X = 2*(v0 + v) + fx;
            #pragma unroll
            for (int rh = 0; rh < 2; rh++) {
                int o = o0 + m0 + mm*16 + (lane >> 2) + rh*8;
                float s = g_bn2s[o], bb = g_bn2b[o];
                float v0f = acc[mm][nn][rh*2]   * s + bb;
                float v1f = acc[mm][nn][rh*2+1] * s + bb;
                float* ob = &out[(((size_t)b*CO + o)*HO + Y)*WO + X];
                ob[0] = v0f > 0.f ? v0f : 0.f;
                ob[2] = v1f > 0.f ? v1f : 0.f;
            }
        }
    }
}

// ---------------- launch ----------------
extern "C" void kernel_launch(void* const* d_in, const int* in_sizes, int n_in,
                              void* d_out, int out_size) {
    const float* x      = (const float*)d_in[0];
    const float* w_off  = (const float*)d_in[1];
    const float* b_off  = (const float*)d_in[2];
    const float* w_mod  = (const float*)d_in[3];
    const float* b_mod  = (const float*)d_in[4];
    const float* w_reg  = (const float*)d_in[5];
    const float* bn1_g  = (const float*)d_in[6];
    const float* bn1_b  = (const float*)d_in[7];
    const float* bn1_m  = (const float*)d_in[8];
    const float* bn1_v  = (const float*)d_in[9];
    const float* w_up   = (const float*)d_in[10];
    const float* bn2_g  = (const float*)d_in[11];
    const float* bn2_b  = (const float*)d_in[12];
    const float* bn2_m  = (const float*)d_in[13];
    const float* bn2_v  = (const float*)d_in[14];
    float* out = (float*)d_out;

    cudaFuncSetAttribute(k_deform, cudaFuncAttributeMaxDynamicSharedMemorySize, D_SMEM);
    cudaFuncSetAttribute(k_up,     cudaFuncAttributeMaxDynamicSharedMemorySize, U_SMEM);

    prep_bn<<<1, 256>>>(bn1_g, bn1_b, bn1_m, bn1_v, bn2_g, bn2_b, bn2_m, bn2_v);
    prep_w<<<1024, 256>>>(w_off, w_mod, w_reg, w_up);
    k_offconv<<<dim3(64, BATCH), 256>>>(x, b_off, b_mod);
    k_coef<<<(BATCH*K2*HWX + 255)/256, 256>>>();
    k_deform<<<dim3(32, 2, BATCH), 256, D_SMEM>>>(x);
    k_up<<<dim3(32, 2, BATCH*4), 256, U_SMEM>>>(out);
}

// round 14
// speedup vs baseline: 1.4682x; 1.4682x over previous
#include <cuda_runtime.h>
#include <cuda_bf16.h>
#include <math.h>
#include <stdint.h>

#define BATCH 8
#define CIN   256
#define HH    64
#define WW    64
#define HWX   4096
#define CO    256
#define K2    9
#define KTOT  2304
#define HO    128
#define WO    128

// ---------------- scratch ----------------
__device__ __align__(16) float    g_wcombT[KTOT*32];
__device__ __align__(16) unsigned g_wAh[CO*KTOT/2];    // deform weights hi plane [o][k/2]
__device__ __align__(16) unsigned g_wAl[CO*KTOT/2];    // lo plane
__device__ __align__(16) unsigned g_wupH[4*CO*512];    // up weights hi plane [ph][o][k/2]
__device__ __align__(16) unsigned g_wupL[4*CO*512];    // lo plane
__device__ float g_bn1s[CO], g_bn1b[CO], g_bn2s[CO], g_bn2b[CO];
__device__ __align__(16) float  g_offmask[BATCH*27*HWX];
__device__ __align__(16) float4 g_cw[BATCH*K2*HWX];
__device__ __align__(16) uint2  g_ci[BATCH*K2*HWX];
__device__ __align__(16) unsigned g_h1p[BATCH*CO*HWX]; // h1 packed bf16 hi|lo

// ---------------- helpers ----------------
__device__ __forceinline__ unsigned packbf(float v) {
    __nv_bfloat16 h = __float2bfloat16(v);
    float r = v - __bfloat162float(h);
    __nv_bfloat16 l = __float2bfloat16(r);
    return (unsigned)__bfloat16_as_ushort(h) | ((unsigned)__bfloat16_as_ushort(l) << 16);
}
__device__ __forceinline__ uint32_t smem_u32(const void* p) {
    uint32_t a;
    asm("{ .reg .u64 t; cvta.to.shared.u64 t, %1; cvt.u32.u64 %0, t; }" : "=r"(a) : "l"(p));
    return a;
}
__device__ __forceinline__ uint32_t swz(uint32_t off) { return off ^ ((off >> 3) & 0x70); }

__device__ __forceinline__ void ldm4(uint32_t* r, uint32_t addr) {
    asm volatile("ldmatrix.sync.aligned.m8n8.x4.shared.b16 {%0,%1,%2,%3}, [%4];"
        : "=r"(r[0]), "=r"(r[1]), "=r"(r[2]), "=r"(r[3]) : "r"(addr));
}
__device__ __forceinline__ void mma_bf16(float* d, const uint32_t* a, uint32_t b0, uint32_t b1) {
    asm volatile("mma.sync.aligned.m16n8k16.row.col.f32.bf16.bf16.f32 "
        "{%0,%1,%2,%3}, {%4,%5,%6,%7}, {%8,%9}, {%0,%1,%2,%3};"
        : "+f"(d[0]), "+f"(d[1]), "+f"(d[2]), "+f"(d[3])
        : "r"(a[0]), "r"(a[1]), "r"(a[2]), "r"(a[3]), "r"(b0), "r"(b1));
}
__device__ __forceinline__ void cpa16(uint32_t dst, const void* src) {
    asm volatile("cp.async.cg.shared.global [%0], [%1], 16;" :: "r"(dst), "l"(src));
}
#define CPA_COMMIT() asm volatile("cp.async.commit_group;" ::: "memory")
#define CPA_WAIT0()  asm volatile("cp.async.wait_group 0;" ::: "memory")

// ---------------- prep: BN fold ----------------
__global__ void prep_bn(const float* __restrict__ g1, const float* __restrict__ b1,
                        const float* __restrict__ m1, const float* __restrict__ v1,
                        const float* __restrict__ g2, const float* __restrict__ b2,
                        const float* __restrict__ m2, const float* __restrict__ v2) {
    int o = threadIdx.x;
    float s1 = g1[o] * rsqrtf(v1[o] + 1e-5f);
    g_bn1s[o] = s1;  g_bn1b[o] = b1[o] - m1[o]*s1;
    float s2 = g2[o] * rsqrtf(v2[o] + 1e-5f);
    g_bn2s[o] = s2;  g_bn2b[o] = b2[o] - m2[o]*s2;
}

// ---------------- prep: weight reorg + bf16 hi/lo plane split ----------------
__global__ void prep_w(const float* __restrict__ w_off, const float* __restrict__ w_mod,
                       const float* __restrict__ w_reg, const float* __restrict__ w_up) {
    int tid = blockIdx.x*blockDim.x + threadIdx.x;
    int nt  = gridDim.x*blockDim.x;
    for (int i = tid; i < KTOT*32; i += nt) {
        int kidx = i >> 5, o = i & 31;
        float v = 0.f;
        if (o < 18)      v = w_off[o*KTOT + kidx];
        else if (o < 27) v = w_mod[(o-18)*KTOT + kidx];
        g_wcombT[i] = v;
    }
    for (int i = tid; i < CO*KTOT/2; i += nt) {
        unsigned p0 = packbf(w_reg[2*i]);
        unsigned p1 = packbf(w_reg[2*i+1]);
        g_wAh[i] = __byte_perm(p0, p1, 0x5410);
        g_wAl[i] = __byte_perm(p0, p1, 0x7632);
    }
    for (int i = tid; i < 4*CO*512; i += nt) {
        int pr = i & 511;
        int o  = (i >> 9) & 255;
        int ph = i >> 17;
        int fy = ph >> 1, fx = ph & 1;
        unsigned pp[2];
        #pragma unroll
        for (int s2 = 0; s2 < 2; s2++) {
            int kidx = pr*2 + s2;
            int ci = kidx >> 2, tt = kidx & 3;
            int ty = tt >> 1, tx = tt & 1;
            int ky = fy ? (ty ? 0 : 2) : (ty ? 3 : 1);
            int kx = fx ? (tx ? 0 : 2) : (tx ? 3 : 1);
            pp[s2] = packbf(w_up[((ci*CO + o)*4 + ky)*4 + kx]);
        }
        g_wupH[i] = __byte_perm(pp[0], pp[1], 0x5410);
        g_wupL[i] = __byte_perm(pp[0], pp[1], 0x7632);
    }
}

// ---------------- kernel 1: offset + mask conv (verified) ----------------
__global__ void __launch_bounds__(256) k_offconv(const float* __restrict__ x,
                                                 const float* __restrict__ b_off,
                                                 const float* __restrict__ b_mod) {
    int h = blockIdx.x;
    int b = blockIdx.y;
    int t = threadIdx.x;
    __shared__ float4 sW4[16][8];
    __shared__ float2 sV2[16][32];
    float* sW = (float*)sW4;
    float* sV = (float*)sV2;
    int ox = t & 7, py = t >> 3;
    float acc[4][2] = {};
    const float* xb = x + (size_t)b*CIN*HWX;
    for (int t0 = 0; t0 < KTOT; t0 += 16) {
        #pragma unroll
        for (int i = 0; i < 2; i++) {
            int e = t + i*256;
            int r = e >> 5, col = e & 31;
            sW[r*32 + col] = g_wcombT[(t0+r)*32 + col];
        }
        #pragma unroll
        for (int i = 0; i < 4; i++) {
            int e = t + i*256;
            int r = e >> 6, pl = e & 63;
            int kidx = t0 + r;
            int c  = kidx / 9;
            int kk = kidx - c*9;
            int ky = kk / 3;
            int kx = kk - ky*3;
            int yy = h + ky - 1;
            int xx = pl + kx - 1;
            float v = 0.f;
            if (yy >= 0 && yy < HH && xx >= 0 && xx < WW)
                v = xb[c*HWX + yy*WW + xx];
            sV[r*64 + pl] = v;
        }
        __syncthreads();
        #pragma unroll
        for (int r = 0; r < 16; r++) {
            float4 a  = sW4[r][ox];
            float2 bv = sV2[r][py];
            acc[0][0] += a.x*bv.x; acc[0][1] += a.x*bv.y;
            acc[1][0] += a.y*bv.x; acc[1][1] += a.y*bv.y;
            acc[2][0] += a.z*bv.x; acc[2][1] += a.z*bv.y;
            acc[3][0] += a.w*bv.x; acc[3][1] += a.w*bv.y;
        }
        __syncthreads();
    }
    #pragma unroll
    for (int i = 0; i < 4; i++) {
        int o = ox*4 + i;
        if (o < 27) {
            float bias = (o < 18) ? b_off[o] : b_mod[o-18];
            #pragma unroll
            for (int j = 0; j < 2; j++) {
                int p = h*WW + py*2 + j;
                g_offmask[((size_t)b*27 + o)*HWX + p] = acc[i][j] + bias;
            }
        }
    }
}

// ---------------- kernel 1b: bilinear coefficients (verified) ----------------
__global__ void k_coef() {
    int tid = blockIdx.x*blockDim.x + threadIdx.x;
    if (tid >= BATCH*K2*HWX) return;
    int p = tid & (HWX-1);
    int k = (tid >> 12) % 9;
    int b = tid / (K2*HWX);
    const float* om = g_offmask + (size_t)b*27*HWX;
    float oyv = om[(2*k  )*HWX + p];
    float oxv = om[(2*k+1)*HWX + p];
    float z   = om[(18+k )*HWX + p];
    float m = 2.f / (1.f + expf(-z));
    int hh = p >> 6, ww = p & 63;
    float py = (float)hh - 1.f + (float)(k/3) + oyv;
    float px = (float)ww - 1.f + (float)(k%3) + oxv;
    float y0f = floorf(py), x0f = floorf(px);
    float wy1 = py - y0f,  wx1 = px - x0f;
    int y0 = (int)y0f, x0 = (int)x0f;
    int y1 = y0 + 1, x1 = x0 + 1;
    float wy0m = (y0 >= 0 && y0 < HH) ? (1.f - wy1)*m : 0.f;
    float wy1m = (y1 >= 0 && y1 < HH) ? wy1*m : 0.f;
    float wx0v = (x0 >= 0 && x0 < WW) ? (1.f - wx1) : 0.f;
    float wx1v = (x1 >= 0 && x1 < WW) ? wx1 : 0.f;
    int y0c = min(max(y0,0),HH-1), y1c = min(max(y1,0),HH-1);
    int x0c = min(max(x0,0),WW-1), x1c = min(max(x1,0),WW-1);
    float4 cw; cw.x = wy0m; cw.y = wy1m; cw.z = wx0v; cw.w = wx1v;
    g_cw[tid] = cw;
    uint2 ci;
    ci.x = (unsigned)(y0c*WW + x0c) | ((unsigned)(y0c*WW + x1c) << 16);
    ci.y = (unsigned)(y1c*WW + x0c) | ((unsigned)(y1c*WW + x1c) << 16);
    g_ci[tid] = ci;
}

// ================= GEMM tile geometry (R10 geometry: 512 thr, M=256 x N=128) =================
#define BUFS   98304
#define AH_OFF 0
#define AL_OFF 32768
#define BH_OFF 65536
#define BL_OFF 81920
#define D_CW   (2*BUFS)
#define D_CI   (2*BUFS + 18432)
#define D_SMEM (2*BUFS + 18432 + 9216 + 1024)
#define U_SMEM (2*BUFS + 1024)

// ---------------- kernel 2: deform conv GEMM (HMMA, gather/MMA interleaved) ----------------
__global__ void __launch_bounds__(512) k_deform(const float* __restrict__ x) {
    extern __shared__ __align__(16) char smem[];
    uint32_t sraw = smem_u32(smem);
    uint32_t s0 = (sraw + 1023) & ~1023u;
    char* Bp = smem + (s0 - sraw);
    const int p0 = blockIdx.x * 128;
    const int b  = blockIdx.y;
    const int t  = threadIdx.x;
    const int w  = t >> 5, lane = t & 31;
    const int m0 = (w >> 2) * 64, n0 = (w & 3) * 32;

    float4* sCW = (float4*)(Bp + D_CW);
    uint2*  sCI = (uint2*) (Bp + D_CI);
    for (int e = t; e < K2*128; e += 512) {
        int kk = e >> 7, pl = e & 127;
        int gi = (b*K2 + kk)*HWX + p0 + pl;
        sCW[e] = g_cw[gi];
        sCI[e] = g_ci[gi];
    }
    const float* xb = x + (size_t)b*CIN*HWX;
    float acc[4][4][4] = {};
    const int fpl = t & 127;
    const int fkq = t >> 7;            // 0..3, 8 k-pairs each

    auto fillA = [&](int ch, int buf) {
        int t0h = ch * 32;
        #pragma unroll
        for (int i = 0; i < 8; i++) {
            int e = t + i*512;
            int plane = e >> 11;
            int rem = e & 2047;
            int orow = rem >> 3, seg = rem & 7;
            const unsigned* srcb = plane ? g_wAl : g_wAh;
            const void* src = &srcb[orow*(KTOT/2) + t0h + seg*4];
            uint32_t dst = s0 + buf*BUFS + (plane ? AL_OFF : AH_OFF) + swz((unsigned)(orow*128 + seg*16));
            cpa16(dst, src);
        }
    };
    auto fillB = [&](int ch, int buf) {      // prologue only
        int t0 = ch * 64;
        char* base = Bp + buf*BUFS;
        #pragma unroll
        for (int kp = 0; kp < 8; kp++) {
            int kpi = fkq*8 + kp;
            float v[2];
            #pragma unroll
            for (int s2 = 0; s2 < 2; s2++) {
                int kidx = t0 + kpi*2 + s2;
                int c = kidx / 9;
                int kk = kidx - c*9;
                float4 cw = sCW[kk*128 + fpl];
                uint2  ci = sCI[kk*128 + fpl];
                const float* xc = xb + c*HWX;
                v[s2] = cw.x*(cw.z*xc[ci.x & 0xFFFF] + cw.w*xc[ci.x >> 16])
                      + cw.y*(cw.z*xc[ci.y & 0xFFFF] + cw.w*xc[ci.y >> 16]);
            }
            unsigned pw0 = packbf(v[0]), pw1 = packbf(v[1]);
            unsigned off = swz((unsigned)(fpl*128 + kpi*4));
            *(unsigned*)(base + BH_OFF + off) = __byte_perm(pw0, pw1, 0x5410);
            *(unsigned*)(base + BL_OFF + off) = __byte_perm(pw0, pw1, 0x7632);
        }
    };
    // fused: MMA on cur buffer, interleaving next-chunk gathers per ks-step
    auto fused = [&](int cur, int ch_n, int nxt, bool dn) {
        uint32_t sb = s0 + cur*BUFS;
        char* nbase = Bp + nxt*BUFS;
        int t0n = ch_n * 64;
        const int lrow = lane & 15;
        const int lkb  = (lane >> 4) * 16;
        #pragma unroll
        for (int ks = 0; ks < 4; ks++) {
            // 1) issue gathers for group ks of next chunk (16 loads in flight)
            float g[16];
            int kkv[4];
            if (dn) {
                #pragma unroll
                for (int j = 0; j < 2; j++) {
                    int kpi = fkq*8 + ks*2 + j;
                    #pragma unroll
                    for (int s2 = 0; s2 < 2; s2++) {
                        int kidx = t0n + kpi*2 + s2;
                        int c = kidx / 9;
                        int kk = kidx - c*9;
                        kkv[j*2+s2] = kk;
                        uint2 ci = sCI[kk*128 + fpl];
                        const float* xc = xb + c*HWX;
                        int e = (j*2+s2)*4;
                        g[e+0] = xc[ci.x & 0xFFFF];
                        g[e+1] = xc[ci.x >> 16];
                        g[e+2] = xc[ci.y & 0xFFFF];
                        g[e+3] = xc[ci.y >> 16];
                    }
                }
            }
            // 2) MMA block for ks on current buffer
            int kb = ks*32 + lkb;
            uint32_t bh[2][4], bl[2][4];
            #pragma unroll
            for (int nn16 = 0; nn16 < 2; nn16++) {
                uint32_t roff = (uint32_t)((n0 + nn16*16 + lrow)*128 + kb);
                ldm4(bh[nn16], sb + BH_OFF + swz(roff));
                ldm4(bl[nn16], sb + BL_OFF + swz(roff));
            }
            #pragma unroll
            for (int mm = 0; mm < 4; mm++) {
                uint32_t aoff = (uint32_t)((m0 + mm*16 + lrow)*128 + kb);
                uint32_t ah[4], al[4];
                ldm4(ah, sb + AH_OFF + swz(aoff));
                ldm4(al, sb + AL_OFF + swz(aoff));
                #pragma unroll
                for (int nn = 0; nn < 4; nn++) {
                    uint32_t b0h = bh[nn>>1][nn&1], b1h = bh[nn>>1][2+(nn&1)];
                    uint32_t b0l = bl[nn>>1][nn&1], b1l = bl[nn>>1][2+(nn&1)];
                    mma_bf16(acc[mm][nn], ah, b0h, b1h);
                    mma_bf16(acc[mm][nn], al, b0h, b1h);
                    mma_bf16(acc[mm][nn], ah, b0l, b1l);
                }
            }
            // 3) combine + pack + store gathered group into next buffer
            if (dn) {
                #pragma unroll
                for (int j = 0; j < 2; j++) {
                    int kpi = fkq*8 + ks*2 + j;
                    unsigned pw[2];
                    #pragma unroll
                    for (int s2 = 0; s2 < 2; s2++) {
                        float4 cw = sCW[kkv[j*2+s2]*128 + fpl];
                        int e = (j*2+s2)*4;
                        float v = cw.x*(cw.z*g[e] + cw.w*g[e+1]) + cw.y*(cw.z*g[e+2] + cw.w*g[e+3]);
                        pw[s2] = packbf(v);
                    }
                    unsigned off = swz((unsigned)(fpl*128 + kpi*4));
                    *(unsigned*)(nbase + BH_OFF + off) = __byte_perm(pw[0], pw[1], 0x5410);
                    *(unsigned*)(nbase + BL_OFF + off) = __byte_perm(pw[0], pw[1], 0x7632);
                }
            }
        }
    };

    __syncthreads();          // coef tiles ready
    fillA(0, 0); CPA_COMMIT();
    fillB(0, 0);
    CPA_WAIT0();
    __syncthreads();
    for (int ch = 0; ch < 36; ch++) {
        int cur = ch & 1, nxt = cur ^ 1;
        if (ch < 35) { fillA(ch+1, nxt); CPA_COMMIT(); }
        fused(cur, ch+1, nxt, ch < 35);
        CPA_WAIT0();
        __syncthreads();
    }
    // epilogue: BN1 + ReLU + pack
    #pragma unroll
    for (int mm = 0; mm < 4; mm++) {
        #pragma unroll
        for (int nn = 0; nn < 4; nn++) {
            int c0 = n0 + nn*8 + 2*(lane & 3);
            #pragma unroll
            for (int rh = 0; rh < 2; rh++) {
                int o = m0 + mm*16 + (lane >> 2) + rh*8;
                float s = g_bn1s[o], bb = g_bn1b[o];
                float v0 = acc[mm][nn][rh*2]   * s + bb;
                float v1 = acc[mm][nn][rh*2+1] * s + bb;
                v0 = v0 > 0.f ? v0 : 0.f;
                v1 = v1 > 0.f ? v1 : 0.f;
                uint2 st; st.x = packbf(v0); st.y = packbf(v1);
                *(uint2*)&g_h1p[(((size_t)b*CO + o) << 12) + p0 + c0] = st;
            }
        }
    }
}

// ---------------- kernel 3: transposed conv GEMM (HMMA, interleaved) ----------------
__global__ void __launch_bounds__(512) k_up(float* __restrict__ out) {
    extern __shared__ __align__(16) char smem[];
    uint32_t sraw = smem_u32(smem);
    uint32_t s0 = (sraw + 1023) & ~1023u;
    char* Bp = smem + (s0 - sraw);
    const int bx = blockIdx.x;
    const int bz = blockIdx.y;
    const int b = bz >> 2, ph = bz & 3;
    const int fy = ph >> 1, fx = ph & 1;
    const int u0 = (bx >> 2) * 8, v0 = (bx & 3) * 16;
    const int dy1 = fy ? 1 : -1, dx1 = fx ? 1 : -1;
    const int t = threadIdx.x;
    const int w = t >> 5, lane = t & 31;
    const int m0 = (w >> 2) * 64, n0 = (w & 3) * 32;

    const unsigned* h1b = g_h1p + (((size_t)b*CO) << 12);
    const unsigned* wbH = g_wupH + ((size_t)(ph*CO) << 9);
    const unsigned* wbL = g_wupL + ((size_t)(ph*CO) << 9);

    float acc[4][4][4] = {};
    const int fpl = t & 127;
    const int fkq = t >> 7;
    const int fuu = u0 + (fpl >> 4), fvv = v0 + (fpl & 15);

    auto fillA = [&](int ch, int buf) {
        int t0h = ch * 32;
        #pragma unroll
        for (int i = 0; i < 8; i++) {
            int e = t + i*512;
            int plane = e >> 11;
            int rem = e & 2047;
            int orow = rem >> 3, seg = rem & 7;
            const unsigned* srcb = plane ? wbL : wbH;
            const void* src = &srcb[(orow << 9) + t0h + seg*4];
            uint32_t dst = s0 + buf*BUFS + (plane ? AL_OFF : AH_OFF) + swz((unsigned)(orow*128 + seg*16));
            cpa16(dst, src);
        }
    };
    auto fillB = [&](int ch, int buf) {      // prologue only
        int t0 = ch * 64;
        char* base = Bp + buf*BUFS;
        #pragma unroll
        for (int kp = 0; kp < 8; kp++) {
            int kpi = fkq*8 + kp;
            int kidx0 = t0 + kpi*2;
            int ci = kidx0 >> 2;
            const unsigned* hp = h1b + ((size_t)ci << 12);
            unsigned pv[2];
            #pragma unroll
            for (int s2 = 0; s2 < 2; s2++) {
                int tt = (kidx0 + s2) & 3;
                int ty = tt >> 1, tx = tt & 1;
                int yi = fuu + (ty ? dy1 : 0);
                int xi = fvv + (tx ? dx1 : 0);
                pv[s2] = (yi >= 0 && yi < HH && xi >= 0 && xi < WW) ? hp[yi*WW + xi] : 0u;
            }
            unsigned off = swz((unsigned)(fpl*128 + kpi*4));
            *(unsigned*)(base + BH_OFF + off) = __byte_perm(pv[0], pv[1], 0x5410);
            *(unsigned*)(base + BL_OFF + off) = __byte_perm(pv[0], pv[1], 0x7632);
        }
    };
    auto fused = [&](int cur, int ch_n, int nxt, bool dn) {
        uint32_t sb = s0 + cur*BUFS;
        char* nbase = Bp + nxt*BUFS;
        int t0n = ch_n * 64;
        const int lrow = lane & 15;
        const int lkb  = (lane >> 4) * 16;
        #pragma unroll
        for (int ks = 0; ks < 4; ks++) {
            unsigned gp[4];
            if (dn) {
                #pragma unroll
                for (int j = 0; j < 2; j++) {
                    int kpi = fkq*8 + ks*2 + j;
                    int kidx0 = t0n + kpi*2;
                    int ci = kidx0 >> 2;
                    const unsigned* hp = h1b + ((size_t)ci << 12);
                    #pragma unroll
                    for (int s2 = 0; s2 < 2; s2++) {
                        int tt = (kidx0 + s2) & 3;
                        int ty = tt >> 1, tx = tt & 1;
                        int yi = fuu + (ty ? dy1 : 0);
                        int xi = fvv + (tx ? dx1 : 0);
                        gp[j*2+s2] = (yi >= 0 && yi < HH && xi >= 0 && xi < WW) ? hp[yi*WW + xi] : 0u;
                    }
                }
            }
            int kb = ks*32 + lkb;
            uint32_t bh[2][4], bl[2][4];
            #pragma unroll
            for (int nn16 = 0; nn16 < 2; nn16++) {
                uint32_t roff = (uint32_t)((n0 + nn16*16 + lrow)*128 + kb);
                ldm4(bh[nn16], sb + BH_OFF + swz(roff));
                ldm4(bl[nn16], sb + BL_OFF + swz(roff));
            }
            #pragma unroll
            for (int mm = 0; mm < 4; mm++) {
                uint32_t aoff = (uint32_t)((m0 + mm*16 + lrow)*128 + kb);
                uint32_t ah[4], al[4];
                ldm4(ah, sb + AH_OFF + swz(aoff));
                ldm4(al, sb + AL_OFF + swz(aoff));
                #pragma unroll
                for (int nn = 0; nn < 4; nn++) {
                    uint32_t b0h = bh[nn>>1][nn&1], b1h = bh[nn>>1][2+(nn&1)];
                    uint32_t b0l = bl[nn>>1][nn&1], b1l = bl[nn>>1][2+(nn&1)];
                    mma_bf16(acc[mm][nn], ah, b0h, b1h);
                    mma_bf16(acc[mm][nn], al, b0h, b1h);
                    mma_bf16(acc[mm][nn], ah, b0l, b1l);
                }
            }
            if (dn) {
                #pragma unroll
                for (int j = 0; j < 2; j++) {
                    int kpi = fkq*8 + ks*2 + j;
                    unsigned off = swz((unsigned)(fpl*128 + kpi*4));
                    *(unsigned*)(nbase + BH_OFF + off) = __byte_perm(gp[j*2], gp[j*2+1], 0x5410);
                    *(unsigned*)(nbase + BL_OFF + off) = __byte_perm(gp[j*2], gp[j*2+1], 0x7632);
                }
            }
        }
    };

    fillA(0, 0); CPA_COMMIT();
    fillB(0, 0);
    CPA_WAIT0();
    __syncthreads();
    for (int ch = 0; ch < 16; ch++) {
        int cur = ch & 1, nxt = cur ^ 1;
        if (ch < 15) { fillA(ch+1, nxt); CPA_COMMIT(); }
        fused(cur, ch+1, nxt, ch < 15);
        CPA_WAIT0();
        __syncthreads();
    }
    // epilogue: BN2 + ReLU, strided scatter
    #pragma unroll
    for (int mm = 0; mm < 4; mm++) {
        #pragma unroll
        for (int nn = 0; nn < 4; nn++) {
            int c0 = n0 + nn*8 + 2*(lane & 3);
            int u = c0 >> 4, v = c0 & 15;
            int Y = 2*(u0 + u) + fy;
            int X = 2*(v0 + v) + fx;
            #pragma unroll
            for (int rh = 0; rh < 2; rh++) {
                int o = m0 + mm*16 + (lane >> 2) + rh*8;
                float s = g_bn2s[o], bb = g_bn2b[o];
                float v0f = acc[mm][nn][rh*2]   * s + bb;
                float v1f = acc[mm][nn][rh*2+1] * s + bb;
                float* ob = &out[(((size_t)b*CO + o)*HO + Y)*WO + X];
                ob[0] = v0f > 0.f ? v0f : 0.f;
                ob[2] = v1f > 0.f ? v1f : 0.f;
            }
        }
    }
}

// ---------------- launch ----------------
extern "C" void kernel_launch(void* const* d_in, const int* in_sizes, int n_in,
                              void* d_out, int out_size) {
    const float* x      = (const float*)d_in[0];
    const float* w_off  = (const float*)d_in[1];
    const float* b_off  = (const float*)d_in[2];
    const float* w_mod  = (const float*)d_in[3];
    const float* b_mod  = (const float*)d_in[4];
    const float* w_reg  = (const float*)d_in[5];
    const float* bn1_g  = (const float*)d_in[6];
    const float* bn1_b  = (const float*)d_in[7];
    const float* bn1_m  = (const float*)d_in[8];
    const float* bn1_v  = (const float*)d_in[9];
    const float* w_up   = (const float*)d_in[10];
    const float* bn2_g  = (const float*)d_in[11];
    const float* bn2_b  = (const float*)d_in[12];
    const float* bn2_m  = (const float*)d_in[13];
    const float* bn2_v  = (const float*)d_in[14];
    float* out = (float*)d_out;

    cudaFuncSetAttribute(k_deform, cudaFuncAttributeMaxDynamicSharedMemorySize, D_SMEM);
    cudaFuncSetAttribute(k_up,     cudaFuncAttributeMaxDynamicSharedMemorySize, U_SMEM);

    prep_bn<<<1, 256>>>(bn1_g, bn1_b, bn1_m, bn1_v, bn2_g, bn2_b, bn2_m, bn2_v);
    prep_w<<<1024, 256>>>(w_off, w_mod, w_reg, w_up);
    k_offconv<<<dim3(64, BATCH), 256>>>(x, b_off, b_mod);
    k_coef<<<(BATCH*K2*HWX + 255)/256, 256>>>();
    k_deform<<<dim3(32, BATCH), 512, D_SMEM>>>(x);
    k_up<<<dim3(32, BATCH*4), 512, U_SMEM>>>(out);
}

// round 15
// speedup vs baseline: 1.5139x; 1.0311x over previous
#include <cuda_runtime.h>
#include <cuda_bf16.h>
#include <math.h>
#include <stdint.h>

#define BATCH 8
#define CIN   256
#define HH    64
#define WW    64
#define HWX   4096
#define CO    256
#define K2    9
#define KTOT  2304
#define HO    128
#define WO    128
#define NPR   (KTOT/2)   // 1152 k-pairs per o row

// ---------------- scratch ----------------
__device__ __align__(16) float    g_wcombT[KTOT*32];
__device__ __align__(16) unsigned g_wAh[CO*NPR];       // deform weights hi plane, K-order kk*256+c
__device__ __align__(16) unsigned g_wAl[CO*NPR];       // lo plane
__device__ __align__(16) unsigned g_wupH[4*CO*512];    // up weights hi plane [ph][o][k/2]
__device__ __align__(16) unsigned g_wupL[4*CO*512];    // lo plane
__device__ float g_bn1s[CO], g_bn1b[CO], g_bn2s[CO], g_bn2b[CO];
__device__ __align__(16) float  g_offmask[BATCH*27*HWX];
__device__ __align__(16) float4 g_cw[BATCH*K2*HWX];
__device__ __align__(16) uint2  g_ci[BATCH*K2*HWX];
__device__ __align__(16) float  g_xt[(size_t)BATCH*HWX*CIN];  // x transposed channel-last
__device__ __align__(16) unsigned g_h1p[BATCH*CO*HWX]; // h1 packed bf16 hi|lo

// ---------------- helpers ----------------
__device__ __forceinline__ unsigned packbf(float v) {
    __nv_bfloat16 h = __float2bfloat16(v);
    float r = v - __bfloat162float(h);
    __nv_bfloat16 l = __float2bfloat16(r);
    return (unsigned)__bfloat16_as_ushort(h) | ((unsigned)__bfloat16_as_ushort(l) << 16);
}
__device__ __forceinline__ uint32_t smem_u32(const void* p) {
    uint32_t a;
    asm("{ .reg .u64 t; cvta.to.shared.u64 t, %1; cvt.u32.u64 %0, t; }" : "=r"(a) : "l"(p));
    return a;
}
__device__ __forceinline__ uint32_t swz(uint32_t off) { return off ^ ((off >> 3) & 0x70); }

__device__ __forceinline__ void ldm4(uint32_t* r, uint32_t addr) {
    asm volatile("ldmatrix.sync.aligned.m8n8.x4.shared.b16 {%0,%1,%2,%3}, [%4];"
        : "=r"(r[0]), "=r"(r[1]), "=r"(r[2]), "=r"(r[3]) : "r"(addr));
}
__device__ __forceinline__ void mma_bf16(float* d, const uint32_t* a, uint32_t b0, uint32_t b1) {
    asm volatile("mma.sync.aligned.m16n8k16.row.col.f32.bf16.bf16.f32 "
        "{%0,%1,%2,%3}, {%4,%5,%6,%7}, {%8,%9}, {%0,%1,%2,%3};"
        : "+f"(d[0]), "+f"(d[1]), "+f"(d[2]), "+f"(d[3])
        : "r"(a[0]), "r"(a[1]), "r"(a[2]), "r"(a[3]), "r"(b0), "r"(b1));
}
__device__ __forceinline__ void cpa16(uint32_t dst, const void* src) {
    asm volatile("cp.async.cg.shared.global [%0], [%1], 16;" :: "r"(dst), "l"(src));
}
#define CPA_COMMIT() asm volatile("cp.async.commit_group;" ::: "memory")
#define CPA_WAIT0()  asm volatile("cp.async.wait_group 0;" ::: "memory")

// ---------------- prep: BN fold ----------------
__global__ void prep_bn(const float* __restrict__ g1, const float* __restrict__ b1,
                        const float* __restrict__ m1, const float* __restrict__ v1,
                        const float* __restrict__ g2, const float* __restrict__ b2,
                        const float* __restrict__ m2, const float* __restrict__ v2) {
    int o = threadIdx.x;
    float s1 = g1[o] * rsqrtf(v1[o] + 1e-5f);
    g_bn1s[o] = s1;  g_bn1b[o] = b1[o] - m1[o]*s1;
    float s2 = g2[o] * rsqrtf(v2[o] + 1e-5f);
    g_bn2s[o] = s2;  g_bn2b[o] = b2[o] - m2[o]*s2;
}

// ---------------- prep: x transpose to channel-last ----------------
__global__ void __launch_bounds__(256) k_xt(const float* __restrict__ x) {
    __shared__ float tile[32][33];
    int pt = blockIdx.x, ct = blockIdx.y, b = blockIdx.z;
    int tx = threadIdx.x & 31, ty = threadIdx.x >> 5;
    const float* xb = x + ((size_t)b*CIN + ct*32)*HWX + pt*32;
    #pragma unroll
    for (int i = 0; i < 4; i++) {
        int c = ty + i*8;
        tile[c][tx] = xb[(size_t)c*HWX + tx];
    }
    __syncthreads();
    float* xtb = g_xt + ((size_t)b*HWX + pt*32)*CIN + ct*32;
    #pragma unroll
    for (int i = 0; i < 4; i++) {
        int p = ty + i*8;
        xtb[(size_t)p*CIN + tx] = tile[tx][p];
    }
}

// ---------------- prep: weight reorg + bf16 hi/lo plane split ----------------
__global__ void prep_w(const float* __restrict__ w_off, const float* __restrict__ w_mod,
                       const float* __restrict__ w_reg, const float* __restrict__ w_up) {
    int tid = blockIdx.x*blockDim.x + threadIdx.x;
    int nt  = gridDim.x*blockDim.x;
    for (int i = tid; i < KTOT*32; i += nt) {
        int kidx = i >> 5, o = i & 31;
        float v = 0.f;
        if (o < 18)      v = w_off[o*KTOT + kidx];
        else if (o < 27) v = w_mod[(o-18)*KTOT + kidx];
        g_wcombT[i] = v;
    }
    // deform weight planes, permuted K-order: kidx' = kk*256 + c
    for (int i = tid; i < CO*NPR; i += nt) {
        int pr = i % NPR;
        int o  = i / NPR;
        int kk = pr >> 7;          // 0..8
        int cp = pr & 127;         // c pair
        unsigned q0 = packbf(w_reg[o*KTOT + (2*cp  )*9 + kk]);
        unsigned q1 = packbf(w_reg[o*KTOT + (2*cp+1)*9 + kk]);
        g_wAh[i] = __byte_perm(q0, q1, 0x5410);
        g_wAl[i] = __byte_perm(q0, q1, 0x7632);
    }
    for (int i = tid; i < 4*CO*512; i += nt) {
        int pr = i & 511;
        int o  = (i >> 9) & 255;
        int ph = i >> 17;
        int fy = ph >> 1, fx = ph & 1;
        unsigned pp[2];
        #pragma unroll
        for (int s2 = 0; s2 < 2; s2++) {
            int kidx = pr*2 + s2;
            int ci = kidx >> 2, tt = kidx & 3;
            int ty = tt >> 1, tx = tt & 1;
            int ky = fy ? (ty ? 0 : 2) : (ty ? 3 : 1);
            int kx = fx ? (tx ? 0 : 2) : (tx ? 3 : 1);
            pp[s2] = packbf(w_up[((ci*CO + o)*4 + ky)*4 + kx]);
        }
        g_wupH[i] = __byte_perm(pp[0], pp[1], 0x5410);
        g_wupL[i] = __byte_perm(pp[0], pp[1], 0x7632);
    }
}

// ---------------- kernel 1: offset + mask conv (verified) ----------------
__global__ void __launch_bounds__(256) k_offconv(const float* __restrict__ x,
                                                 const float* __restrict__ b_off,
                                                 const float* __restrict__ b_mod) {
    int h = blockIdx.x;
    int b = blockIdx.y;
    int t = threadIdx.x;
    __shared__ float4 sW4[16][8];
    __shared__ float2 sV2[16][32];
    float* sW = (float*)sW4;
    float* sV = (float*)sV2;
    int ox = t & 7, py = t >> 3;
    float acc[4][2] = {};
    const float* xb = x + (size_t)b*CIN*HWX;
    for (int t0 = 0; t0 < KTOT; t0 += 16) {
        #pragma unroll
        for (int i = 0; i < 2; i++) {
            int e = t + i*256;
            int r = e >> 5, col = e & 31;
            sW[r*32 + col] = g_wcombT[(t0+r)*32 + col];
        }
        #pragma unroll
        for (int i = 0; i < 4; i++) {
            int e = t + i*256;
            int r = e >> 6, pl = e & 63;
            int kidx = t0 + r;
            int c  = kidx / 9;
            int kk = kidx - c*9;
            int ky = kk / 3;
            int kx = kk - ky*3;
            int yy = h + ky - 1;
            int xx = pl + kx - 1;
            float v = 0.f;
            if (yy >= 0 && yy < HH && xx >= 0 && xx < WW)
                v = xb[c*HWX + yy*WW + xx];
            sV[r*64 + pl] = v;
        }
        __syncthreads();
        #pragma unroll
        for (int r = 0; r < 16; r++) {
            float4 a  = sW4[r][ox];
            float2 bv = sV2[r][py];
            acc[0][0] += a.x*bv.x; acc[0][1] += a.x*bv.y;
            acc[1][0] += a.y*bv.x; acc[1][1] += a.y*bv.y;
            acc[2][0] += a.z*bv.x; acc[2][1] += a.z*bv.y;
            acc[3][0] += a.w*bv.x; acc[3][1] += a.w*bv.y;
        }
        __syncthreads();
    }
    #pragma unroll
    for (int i = 0; i < 4; i++) {
        int o = ox*4 + i;
        if (o < 27) {
            float bias = (o < 18) ? b_off[o] : b_mod[o-18];
            #pragma unroll
            for (int j = 0; j < 2; j++) {
                int p = h*WW + py*2 + j;
                g_offmask[((size_t)b*27 + o)*HWX + p] = acc[i][j] + bias;
            }
        }
    }
}

// ---------------- kernel 1b: bilinear coefficients (verified) ----------------
__global__ void k_coef() {
    int tid = blockIdx.x*blockDim.x + threadIdx.x;
    if (tid >= BATCH*K2*HWX) return;
    int p = tid & (HWX-1);
    int k = (tid >> 12) % 9;
    int b = tid / (K2*HWX);
    const float* om = g_offmask + (size_t)b*27*HWX;
    float oyv = om[(2*k  )*HWX + p];
    float oxv = om[(2*k+1)*HWX + p];
    float z   = om[(18+k )*HWX + p];
    float m = 2.f / (1.f + expf(-z));
    int hh = p >> 6, ww = p & 63;
    float py = (float)hh - 1.f + (float)(k/3) + oyv;
    float px = (float)ww - 1.f + (float)(k%3) + oxv;
    float y0f = floorf(py), x0f = floorf(px);
    float wy1 = py - y0f,  wx1 = px - x0f;
    int y0 = (int)y0f, x0 = (int)x0f;
    int y1 = y0 + 1, x1 = x0 + 1;
    float wy0m = (y0 >= 0 && y0 < HH) ? (1.f - wy1)*m : 0.f;
    float wy1m = (y1 >= 0 && y1 < HH) ? wy1*m : 0.f;
    float wx0v = (x0 >= 0 && x0 < WW) ? (1.f - wx1) : 0.f;
    float wx1v = (x1 >= 0 && x1 < WW) ? wx1 : 0.f;
    int y0c = min(max(y0,0),HH-1), y1c = min(max(y1,0),HH-1);
    int x0c = min(max(x0,0),WW-1), x1c = min(max(x1,0),WW-1);
    float4 cw; cw.x = wy0m; cw.y = wy1m; cw.z = wx0v; cw.w = wx1v;
    g_cw[tid] = cw;
    uint2 ci;
    ci.x = (unsigned)(y0c*WW + x0c) | ((unsigned)(y0c*WW + x1c) << 16);
    ci.y = (unsigned)(y1c*WW + x0c) | ((unsigned)(y1c*WW + x1c) << 16);
    g_ci[tid] = ci;
}

// ================= GEMM tile geometry (512 thr, M=256 x N=128, KC=64) =================
#define BUFS   98304
#define AH_OFF 0
#define AL_OFF 32768
#define BH_OFF 65536
#define BL_OFF 81920
#define D_CW   (2*BUFS)
#define D_CI   (2*BUFS + 18432)
#define D_SMEM (2*BUFS + 18432 + 9216 + 1024)
#define U_SMEM (2*BUFS + 1024)

// ---------------- kernel 2: deform conv GEMM (HMMA, channel-last coalesced gather) ----------------
// K-order: kidx' = kk*256 + c.  Chunk ch: kk = ch>>2, c0 = (ch&3)*64.
__global__ void __launch_bounds__(512) k_deform() {
    extern __shared__ __align__(16) char smem[];
    uint32_t sraw = smem_u32(smem);
    uint32_t s0 = (sraw + 1023) & ~1023u;
    char* Bp = smem + (s0 - sraw);
    const int p0 = blockIdx.x * 128;
    const int b  = blockIdx.y;
    const int t  = threadIdx.x;
    const int w  = t >> 5, lane = t & 31;
    const int m0 = (w >> 2) * 64, n0 = (w & 3) * 32;

    float4* sCW = (float4*)(Bp + D_CW);
    uint2*  sCI = (uint2*) (Bp + D_CI);
    for (int e = t; e < K2*128; e += 512) {
        int kk = e >> 7, pl = e & 127;
        int gi = (b*K2 + kk)*HWX + p0 + pl;
        sCW[e] = g_cw[gi];
        sCI[e] = g_ci[gi];
    }
    const float* xtb = g_xt + ((size_t)b*HWX)*CIN;
    float acc[4][4][4] = {};
    const int cq = t & 15;          // fill: c quarter (4 c each)
    const int pp = t >> 4;          // fill: p within 32-group (0..31)

    auto fillA = [&](int ch, int buf) {
        int pr0 = (ch >> 2)*128 + (ch & 3)*32;
        #pragma unroll
        for (int i = 0; i < 8; i++) {
            int e = t + i*512;
            int plane = e >> 11;
            int rem = e & 2047;
            int orow = rem >> 3, seg = rem & 7;
            const unsigned* srcb = plane ? g_wAl : g_wAh;
            const void* src = &srcb[orow*NPR + pr0 + seg*4];
            uint32_t dst = s0 + buf*BUFS + (plane ? AL_OFF : AH_OFF) + swz((unsigned)(orow*128 + seg*16));
            cpa16(dst, src);
        }
    };
    // one p-group (32 p) of B fill for chunk (kkn, c0n)
    auto fillBgrp = [&](int kkn, int c0n, char* base, int p) {
        float4 cw = sCW[kkn*128 + p];
        uint2  ci = sCI[kkn*128 + p];
        int cb = c0n + cq*4;
        const float4* r0 = (const float4*)(xtb + (size_t)(ci.x & 0xFFFF)*CIN + cb);
        const float4* r1 = (const float4*)(xtb + (size_t)(ci.x >> 16)   *CIN + cb);
        const float4* r2 = (const float4*)(xtb + (size_t)(ci.y & 0xFFFF)*CIN + cb);
        const float4* r3 = (const float4*)(xtb + (size_t)(ci.y >> 16)   *CIN + cb);
        float4 a0 = *r0, a1 = *r1, a2 = *r2, a3 = *r3;
        float v0 = cw.x*(cw.z*a0.x + cw.w*a1.x) + cw.y*(cw.z*a2.x + cw.w*a3.x);
        float v1 = cw.x*(cw.z*a0.y + cw.w*a1.y) + cw.y*(cw.z*a2.y + cw.w*a3.y);
        float v2 = cw.x*(cw.z*a0.z + cw.w*a1.z) + cw.y*(cw.z*a2.z + cw.w*a3.z);
        float v3 = cw.x*(cw.z*a0.w + cw.w*a1.w) + cw.y*(cw.z*a2.w + cw.w*a3.w);
        unsigned q0 = packbf(v0), q1 = packbf(v1), q2 = packbf(v2), q3 = packbf(v3);
        unsigned off = swz((unsigned)(p*128 + cq*8));
        *(unsigned*)(base + BH_OFF + off)     = __byte_perm(q0, q1, 0x5410);
        *(unsigned*)(base + BH_OFF + off + 4) = __byte_perm(q2, q3, 0x5410);
        *(unsigned*)(base + BL_OFF + off)     = __byte_perm(q0, q1, 0x7632);
        *(unsigned*)(base + BL_OFF + off + 4) = __byte_perm(q2, q3, 0x7632);
    };
    auto fillB = [&](int ch, int buf) {      // prologue: all 128 p
        int kkn = ch >> 2, c0n = (ch & 3)*64;
        char* base = Bp + buf*BUFS;
        #pragma unroll
        for (int ps = 0; ps < 4; ps++)
            fillBgrp(kkn, c0n, base, ps*32 + pp);
    };
    // fused: MMA on cur buffer, one B p-group per ks for next chunk
    auto fused = [&](int cur, int ch_n, int nxt, bool dn) {
        uint32_t sb = s0 + cur*BUFS;
        char* nbase = Bp + nxt*BUFS;
        int kkn = ch_n >> 2, c0n = (ch_n & 3)*64;
        const int lrow = lane & 15;
        const int lkb  = (lane >> 4) * 16;
        #pragma unroll
        for (int ks = 0; ks < 4; ks++) {
            // 1) gather + combine + store one 32-p group of next chunk
            if (dn) fillBgrp(kkn, c0n, nbase, ks*32 + pp);
            // 2) MMA block for ks on current buffer
            int kb = ks*32 + lkb;
            uint32_t bh[2][4], bl[2][4];
            #pragma unroll
            for (int nn16 = 0; nn16 < 2; nn16++) {
                uint32_t roff = (uint32_t)((n0 + nn16*16 + lrow)*128 + kb);
                ldm4(bh[nn16], sb + BH_OFF + swz(roff));
                ldm4(bl[nn16], sb + BL_OFF + swz(roff));
            }
            #pragma unroll
            for (int mm = 0; mm < 4; mm++) {
                uint32_t aoff = (uint32_t)((m0 + mm*16 + lrow)*128 + kb);
                uint32_t ah[4], al[4];
                ldm4(ah, sb + AH_OFF + swz(aoff));
                ldm4(al, sb + AL_OFF + swz(aoff));
                #pragma unroll
                for (int nn = 0; nn < 4; nn++) {
                    uint32_t b0h = bh[nn>>1][nn&1], b1h = bh[nn>>1][2+(nn&1)];
                    uint32_t b0l = bl[nn>>1][nn&1], b1l = bl[nn>>1][2+(nn&1)];
                    mma_bf16(acc[mm][nn], ah, b0h, b1h);
                    mma_bf16(acc[mm][nn], al, b0h, b1h);
                    mma_bf16(acc[mm][nn], ah, b0l, b1l);
                }
            }
        }
    };

    __syncthreads();          // coef tiles ready
    fillA(0, 0); CPA_COMMIT();
    fillB(0, 0);
    CPA_WAIT0();
    __syncthreads();
    for (int ch = 0; ch < 36; ch++) {
        int cur = ch & 1, nxt = cur ^ 1;
        if (ch < 35) { fillA(ch+1, nxt); CPA_COMMIT(); }
        fused(cur, ch+1, nxt, ch < 35);
        CPA_WAIT0();
        __syncthreads();
    }
    // epilogue: BN1 + ReLU + pack
    #pragma unroll
    for (int mm = 0; mm < 4; mm++) {
        #pragma unroll
        for (int nn = 0; nn < 4; nn++) {
            int c0 = n0 + nn*8 + 2*(lane & 3);
            #pragma unroll
            for (int rh = 0; rh < 2; rh++) {
                int o = m0 + mm*16 + (lane >> 2) + rh*8;
                float s = g_bn1s[o], bb = g_bn1b[o];
                float v0 = acc[mm][nn][rh*2]   * s + bb;
                float v1 = acc[mm][nn][rh*2+1] * s + bb;
                v0 = v0 > 0.f ? v0 : 0.f;
                v1 = v1 > 0.f ? v1 : 0.f;
                uint2 st; st.x = packbf(v0); st.y = packbf(v1);
                *(uint2*)&g_h1p[(((size_t)b*CO + o) << 12) + p0 + c0] = st;
            }
        }
    }
}

// ---------------- kernel 3: transposed conv GEMM (HMMA, interleaved, unchanged R14) ----------------
__global__ void __launch_bounds__(512) k_up(float* __restrict__ out) {
    extern __shared__ __align__(16) char smem[];
    uint32_t sraw = smem_u32(smem);
    uint32_t s0 = (sraw + 1023) & ~1023u;
    char* Bp = smem + (s0 - sraw);
    const int bx = blockIdx.x;
    const int bz = blockIdx.y;
    const int b = bz >> 2, ph = bz & 3;
    const int fy = ph >> 1, fx = ph & 1;
    const int u0 = (bx >> 2) * 8, v0 = (bx & 3) * 16;
    const int dy1 = fy ? 1 : -1, dx1 = fx ? 1 : -1;
    const int t = threadIdx.x;
    const int w = t >> 5, lane = t & 31;
    const int m0 = (w >> 2) * 64, n0 = (w & 3) * 32;

    const unsigned* h1b = g_h1p + (((size_t)b*CO) << 12);
    const unsigned* wbH = g_wupH + ((size_t)(ph*CO) << 9);
    const unsigned* wbL = g_wupL + ((size_t)(ph*CO) << 9);

    float acc[4][4][4] = {};
    const int fpl = t & 127;
    const int fkq = t >> 7;
    const int fuu = u0 + (fpl >> 4), fvv = v0 + (fpl & 15);

    auto fillA = [&](int ch, int buf) {
        int t0h = ch * 32;
        #pragma unroll
        for (int i = 0; i < 8; i++) {
            int e = t + i*512;
            int plane = e >> 11;
            int rem = e & 2047;
            int orow = rem >> 3, seg = rem & 7;
            const unsigned* srcb = plane ? wbL : wbH;
            const void* src = &srcb[(orow << 9) + t0h + seg*4];
            uint32_t dst = s0 + buf*BUFS + (plane ? AL_OFF : AH_OFF) + swz((unsigned)(orow*128 + seg*16));
            cpa16(dst, src);
        }
    };
    auto fillB = [&](int ch, int buf) {
        int t0 = ch * 64;
        char* base = Bp + buf*BUFS;
        #pragma unroll
        for (int kp = 0; kp < 8; kp++) {
            int kpi = fkq*8 + kp;
            int kidx0 = t0 + kpi*2;
            int ci = kidx0 >> 2;
            const unsigned* hp = h1b + ((size_t)ci << 12);
            unsigned pv[2];
            #pragma unroll
            for (int s2 = 0; s2 < 2; s2++) {
                int tt = (kidx0 + s2) & 3;
                int ty = tt >> 1, tx = tt & 1;
                int yi = fuu + (ty ? dy1 : 0);
                int xi = fvv + (tx ? dx1 : 0);
                pv[s2] = (yi >= 0 && yi < HH && xi >= 0 && xi < WW) ? hp[yi*WW + xi] : 0u;
            }
            unsigned off = swz((unsigned)(fpl*128 + kpi*4));
            *(unsigned*)(base + BH_OFF + off) = __byte_perm(pv[0], pv[1], 0x5410);
            *(unsigned*)(base + BL_OFF + off) = __byte_perm(pv[0], pv[1], 0x7632);
        }
    };
    auto fused = [&](int cur, int ch_n, int nxt, bool dn) {
        uint32_t sb = s0 + cur*BUFS;
        char* nbase = Bp + nxt*BUFS;
        int t0n = ch_n * 64;
        const int lrow = lane & 15;
        const int lkb  = (lane >> 4) * 16;
        #pragma unroll
        for (int ks = 0; ks < 4; ks++) {
            unsigned gp[4];
            if (dn) {
                #pragma unroll
                for (int j = 0; j < 2; j++) {
                    int kpi = fkq*8 + ks*2 + j;
                    int kidx0 = t0n + kpi*2;
                    int ci = kidx0 >> 2;
                    const unsigned* hp = h1b + ((size_t)ci << 12);
                    #pragma unroll
                    for (int s2 = 0; s2 < 2; s2++) {
                        int tt = (kidx0 + s2) & 3;
                        int ty = tt >> 1, tx = tt & 1;
                        int yi = fuu + (ty ? dy1 : 0);
                        int xi = fvv + (tx ? dx1 : 0);
                        gp[j*2+s2] = (yi >= 0 && yi < HH && xi >= 0 && xi < WW) ? hp[yi*WW + xi] : 0u;
                    }
                }
            }
            int kb = ks*32 + lkb;
            uint32_t bh[2][4], bl[2][4];
            #pragma unroll
            for (int nn16 = 0; nn16 < 2; nn16++) {
                uint32_t roff = (uint32_t)((n0 + nn16*16 + lrow)*128 + kb);
                ldm4(bh[nn16], sb + BH_OFF + swz(roff));
                ldm4(bl[nn16], sb + BL_OFF + swz(roff));
            }
            #pragma unroll
            for (int mm = 0; mm < 4; mm++) {
                uint32_t aoff = (uint32_t)((m0 + mm*16 + lrow)*128 + kb);
                uint32_t ah[4], al[4];
                ldm4(ah, sb + AH_OFF + swz(aoff));
                ldm4(al, sb + AL_OFF + swz(aoff));
                #pragma unroll
                for (int nn = 0; nn < 4; nn++) {
                    uint32_t b0h = bh[nn>>1][nn&1], b1h = bh[nn>>1][2+(nn&1)];
                    uint32_t b0l = bl[nn>>1][nn&1], b1l = bl[nn>>1][2+(nn&1)];
                    mma_bf16(acc[mm][nn], ah, b0h, b1h);
                    mma_bf16(acc[mm][nn], al, b0h, b1h);
                    mma_bf16(acc[mm][nn], ah, b0l, b1l);
                }
            }
            if (dn) {
                #pragma unroll
                for (int j = 0; j < 2; j++) {
                    int kpi = fkq*8 + ks*2 + j;
                    unsigned off = swz((unsigned)(fpl*128 + kpi*4));
                    *(unsigned*)(nbase + BH_OFF + off) = __byte_perm(gp[j*2], gp[j*2+1], 0x5410);
                    *(unsigned*)(nbase + BL_OFF + off) = __byte_perm(gp[j*2], gp[j*2+1], 0x7632);
                }
            }
        }
    };

    fillA(0, 0); CPA_COMMIT();
    fillB(0, 0);
    CPA_WAIT0();
    __syncthreads();
    for (int ch = 0; ch < 16; ch++) {
        int cur = ch & 1, nxt = cur ^ 1;
        if (ch < 15) { fillA(ch+1, nxt); CPA_COMMIT(); }
        fused(cur, ch+1, nxt, ch < 15);
        CPA_WAIT0();
        __syncthreads();
    }
    // epilogue: BN2 + ReLU, strided scatter
    #pragma unroll
    for (int mm = 0; mm < 4; mm++) {
        #pragma unroll
        for (int nn = 0; nn < 4; nn++) {
            int c0 = n0 + nn*8 + 2*(lane & 3);
            int u = c0 >> 4, v = c0 & 15;
            int Y = 2*(u0 + u) + fy;
            int X = 2*(v0 + v) + fx;
            #pragma unroll
            for (int rh = 0; rh < 2; rh++) {
                int o = m0 + mm*16 + (lane >> 2) + rh*8;
                float s = g_bn2s[o], bb = g_bn2b[o];
                float v0f = acc[mm][nn][rh*2]   * s + bb;
                float v1f = acc[mm][nn][rh*2+1] * s + bb;
                float* ob = &out[(((size_t)b*CO + o)*HO + Y)*WO + X];
                ob[0] = v0f > 0.f ? v0f : 0.f;
                ob[2] = v1f > 0.f ? v1f : 0.f;
            }
        }
    }
}

// ---------------- launch ----------------
extern "C" void kernel_launch(void* const* d_in, const int* in_sizes, int n_in,
                              void* d_out, int out_size) {
    const float* x      = (const float*)d_in[0];
    const float* w_off  = (const float*)d_in[1];
    const float* b_off  = (const float*)d_in[2];
    const float* w_mod  = (const float*)d_in[3];
    const float* b_mod  = (const float*)d_in[4];
    const float* w_reg  = (const float*)d_in[5];
    const float* bn1_g  = (const float*)d_in[6];
    const float* bn1_b  = (const float*)d_in[7];
    const float* bn1_m  = (const float*)d_in[8];
    const float* bn1_v  = (const float*)d_in[9];
    const float* w_up   = (const float*)d_in[10];
    const float* bn2_g  = (const float*)d_in[11];
    const float* bn2_b  = (const float*)d_in[12];
    const float* bn2_m  = (const float*)d_in[13];
    const float* bn2_v  = (const float*)d_in[14];
    float* out = (float*)d_out;

    cudaFuncSetAttribute(k_deform, cudaFuncAttributeMaxDynamicSharedMemorySize, D_SMEM);
    cudaFuncSetAttribute(k_up,     cudaFuncAttributeMaxDynamicSharedMemorySize, U_SMEM);

    prep_bn<<<1, 256>>>(bn1_g, bn1_b, bn1_m, bn1_v, bn2_g, bn2_b, bn2_m, bn2_v);
    prep_w<<<1024, 256>>>(w_off, w_mod, w_reg, w_up);
    k_xt<<<dim3(128, 8, BATCH), 256>>>(x);
    k_offconv<<<dim3(64, BATCH), 256>>>(x, b_off, b_mod);
    k_coef<<<(BATCH*K2*HWX + 255)/256, 256>>>();
    k_deform<<<dim3(32, BATCH), 512, D_SMEM>>>();
    k_up<<<dim3(32, BATCH*4), 512, U_SMEM>>>(out);
}